// round 9
// baseline (speedup 1.0000x reference)
#include <cuda_runtime.h>
#include <cuda_bf16.h>

// Problem constants (B=2, T=256, E=256, H=4)
#define E_DIM  256
#define H_DIM  4
#define EH_DIM 1024
#define BT_DIM 512
#define SPLITK 32
#define PCHUNK 32           // EH_DIM / SPLITK
#define KSTEP  16

typedef unsigned long long u64;

// Packed fp32x2 helpers (sm_100+): one instruction, two fp32 FMAs.
#define PACK2(d, lo, hi) asm("mov.b64 %0, {%1, %2};" : "=l"(d) : "f"(lo), "f"(hi))
#define FMA2(d, a, b)    asm("fma.rn.f32x2 %0, %1, %2, %0;" : "+l"(d) : "l"(a), "l"(b))
#define UNPACK2(lo, hi, s) asm("mov.b64 {%0, %1}, %2;" : "=f"(lo), "=f"(hi) : "l"(s))

// Split-K partials for C[f][e] (plain stores -> deterministic), then reduced.
__device__ float g_Cp[SPLITK][E_DIM * E_DIM];   // 8 MB
__device__ float g_C[E_DIM * E_DIM];            // 256 KB

// ---------------------------------------------------------------------------
// Kernel 1: partial C.  C[f,e] = sum_p Wv[c(p), f] * Wp[e, p]
//   p = d*H + h (Wp-native), c(p) = (p&3)*256 + (p>>2).  Both loads coalesced.
// 128x128 tile, 8x8 micro-tile (f32x2 along f), 256 thr, grid (2,2,SPLITK).
// LDS traffic: 64B per 64 MACs = 1B/MAC -> FMA-pipe bound, not crossbar bound.
// ---------------------------------------------------------------------------
__global__ __launch_bounds__(256) void build_C_kernel(
    const float* __restrict__ Wv,   // [EH, E] row-major
    const float* __restrict__ Wp)   // [E, EH] row-major
{
    __shared__ __align__(16) float sA[KSTEP][128];   // [p_local][f_local]
    __shared__ __align__(16) float sB[KSTEP][132];   // [p_local][e_local] (pad 132)

    const int tid = threadIdx.x;
    const int tx  = tid & 15;       // f group (8 wide)
    const int ty  = tid >> 4;       // e group (8 wide)
    const int f0  = blockIdx.x * 128;
    const int e0  = blockIdx.y * 128;
    const int p0  = blockIdx.z * PCHUNK;

    // 8x8 accumulators, packed in pairs along f: accP[fp][j], fp=0..3 (f pairs), j=0..7
    u64 accP[4][8];
    #pragma unroll
    for (int i = 0; i < 4; i++)
        #pragma unroll
        for (int j = 0; j < 8; j++) PACK2(accP[i][j], 0.0f, 0.0f);

    // Load mappings (2 float4 per thread per tile per operand)
    const int lA_pc = tid >> 4;            // 0..15
    const int lA_f8 = (tid & 15) * 8;      // 0,8,...,120
    const int lB_e  = tid >> 1;            // 0..127
    const int lB_p8 = (tid & 1) * 8;       // 0 or 8

    // --- prefetch iter 0 ---
    float4 pa0, pa1, pb0, pb1;
    {
        int p = p0 + lA_pc;
        int c = ((p & 3) << 8) + (p >> 2);
        const float* arow = &Wv[c * E_DIM + f0 + lA_f8];
        pa0 = *(const float4*)(arow);
        pa1 = *(const float4*)(arow + 4);
        const float* brow = &Wp[(e0 + lB_e) * EH_DIM + p0 + lB_p8];
        pb0 = *(const float4*)(brow);
        pb1 = *(const float4*)(brow + 4);
    }

    #pragma unroll
    for (int it = 0; it < PCHUNK / KSTEP; it++) {
        *(float4*)&sA[lA_pc][lA_f8]     = pa0;
        *(float4*)&sA[lA_pc][lA_f8 + 4] = pa1;
        // B scatter: rows p8..p8+7, column e. Row stride 132 -> distinct banks.
        sB[lB_p8 + 0][lB_e] = pb0.x;
        sB[lB_p8 + 1][lB_e] = pb0.y;
        sB[lB_p8 + 2][lB_e] = pb0.z;
        sB[lB_p8 + 3][lB_e] = pb0.w;
        sB[lB_p8 + 4][lB_e] = pb1.x;
        sB[lB_p8 + 5][lB_e] = pb1.y;
        sB[lB_p8 + 6][lB_e] = pb1.z;
        sB[lB_p8 + 7][lB_e] = pb1.w;
        __syncthreads();

        if (it < PCHUNK / KSTEP - 1) {   // prefetch next tile under compute
            int p = p0 + (it + 1) * KSTEP + lA_pc;
            int c = ((p & 3) << 8) + (p >> 2);
            const float* arow = &Wv[c * E_DIM + f0 + lA_f8];
            pa0 = *(const float4*)(arow);
            pa1 = *(const float4*)(arow + 4);
            const float* brow = &Wp[(e0 + lB_e) * EH_DIM + p0 + (it + 1) * KSTEP + lB_p8];
            pb0 = *(const float4*)(brow);
            pb1 = *(const float4*)(brow + 4);
        }

        #pragma unroll
        for (int ps = 0; ps < KSTEP; ps++) {
            float4 a0 = *(float4*)&sA[ps][tx * 8];
            float4 a1 = *(float4*)&sA[ps][tx * 8 + 4];
            float4 b0 = *(float4*)&sB[ps][ty * 8];
            float4 b1 = *(float4*)&sB[ps][ty * 8 + 4];
            u64 ap[4];
            PACK2(ap[0], a0.x, a0.y);
            PACK2(ap[1], a0.z, a0.w);
            PACK2(ap[2], a1.x, a1.y);
            PACK2(ap[3], a1.z, a1.w);
            float bb[8] = {b0.x, b0.y, b0.z, b0.w, b1.x, b1.y, b1.z, b1.w};
            #pragma unroll
            for (int j = 0; j < 8; j++) {
                u64 bd;
                PACK2(bd, bb[j], bb[j]);
                FMA2(accP[0][j], ap[0], bd);
                FMA2(accP[1][j], ap[1], bd);
                FMA2(accP[2][j], ap[2], bd);
                FMA2(accP[3][j], ap[3], bd);
            }
        }
        __syncthreads();
    }

    // epilogue: 8 rows x 2 STG.128
    float* dst = &g_Cp[blockIdx.z][0];
    #pragma unroll
    for (int i = 0; i < 8; i++) {
        float r[8];
        #pragma unroll
        for (int j = 0; j < 8; j++) {
            float lo, hi;
            UNPACK2(lo, hi, accP[i >> 1][j]);
            r[j] = (i & 1) ? hi : lo;
        }
        int f = f0 + tx * 8 + i;
        float* o = &dst[f * E_DIM + e0 + ty * 8];
        *(float4*)(o)     = make_float4(r[0], r[1], r[2], r[3]);
        *(float4*)(o + 4) = make_float4(r[4], r[5], r[6], r[7]);
    }
}

// ---------------------------------------------------------------------------
// Kernel 2: g_C = sum_z g_Cp[z]   (fixed z order -> deterministic)
// ---------------------------------------------------------------------------
__global__ __launch_bounds__(128) void reduce_C_kernel()
{
    int idx4 = (blockIdx.x * 128 + threadIdx.x) * 4;   // covers 65536 floats
    float4 s = make_float4(0.f, 0.f, 0.f, 0.f);
    #pragma unroll
    for (int z0 = 0; z0 < SPLITK; z0 += 8) {
        float4 v[8];
        #pragma unroll
        for (int z = 0; z < 8; z++)
            v[z] = *(const float4*)&g_Cp[z0 + z][idx4];
        #pragma unroll
        for (int z = 0; z < 8; z++) {
            s.x += v[z].x; s.y += v[z].y; s.z += v[z].z; s.w += v[z].w;
        }
    }
    *(float4*)&g_C[idx4] = s;
}

// ---------------------------------------------------------------------------
// Kernel 3: out[m,e] = sum_f values[m,f] * C[f,e]
// 32x32 tile, 2x2 micro (f32x2 along m), 256 thr, grid (8,16) = 128 CTAs.
// ---------------------------------------------------------------------------
__global__ __launch_bounds__(256) void gemm_out_kernel(
    const float* __restrict__ values,   // [BT, E]
    float* __restrict__ out)            // [BT, E]
{
    __shared__ __align__(8) float sV[16][34];   // [f_local][m]
    __shared__ __align__(8) float sC[16][34];   // [f_local][e]

    const int tid = threadIdx.x;
    const int tx  = tid & 15;      // e pair
    const int ty  = tid >> 4;      // m pair
    const int e0  = blockIdx.x * 32;
    const int m0  = blockIdx.y * 32;

    u64 accj0, accj1;
    PACK2(accj0, 0.0f, 0.0f);
    PACK2(accj1, 0.0f, 0.0f);

    const int lV_m  = tid >> 3;
    const int lV_f2 = (tid & 7) * 2;
    const int lC_f  = tid >> 4;
    const int lC_e2 = (tid & 15) * 2;

    float2 pv = *(const float2*)&values[(m0 + lV_m) * E_DIM + lV_f2];
    float2 pc = *(const float2*)&g_C[lC_f * E_DIM + e0 + lC_e2];

    #pragma unroll
    for (int it = 0; it < E_DIM / 16; it++) {
        sV[lV_f2][lV_m]     = pv.x;
        sV[lV_f2 + 1][lV_m] = pv.y;
        *(float2*)&sC[lC_f][lC_e2] = pc;
        __syncthreads();

        if (it < E_DIM / 16 - 1) {
            int f0 = (it + 1) * 16;
            pv = *(const float2*)&values[(m0 + lV_m) * E_DIM + f0 + lV_f2];
            pc = *(const float2*)&g_C[(f0 + lC_f) * E_DIM + e0 + lC_e2];
        }

        #pragma unroll
        for (int ps = 0; ps < 16; ps++) {
            float2 a = *(float2*)&sV[ps][ty * 2];
            float2 b = *(float2*)&sC[ps][tx * 2];
            u64 a01, bd0, bd1;
            PACK2(a01, a.x, a.y);
            PACK2(bd0, b.x, b.x); FMA2(accj0, a01, bd0);
            PACK2(bd1, b.y, b.y); FMA2(accj1, a01, bd1);
        }
        __syncthreads();
    }

    float o00, o10, o01, o11;
    UNPACK2(o00, o10, accj0);
    UNPACK2(o01, o11, accj1);
    *(float2*)&out[(m0 + ty * 2) * E_DIM + e0 + tx * 2]     = make_float2(o00, o01);
    *(float2*)&out[(m0 + ty * 2 + 1) * E_DIM + e0 + tx * 2] = make_float2(o10, o11);
}

// ---------------------------------------------------------------------------
// softmax over w sums to 1 => out = Vh; only values, Wv, Wp matter.
// Inputs: 0=pos_emb, 1=values, 2=ln_w, 3=ln_b, 4=Wq, 5=Wk, 6=Wv, 7=Wp.
// ---------------------------------------------------------------------------
extern "C" void kernel_launch(void* const* d_in, const int* in_sizes, int n_in,
                              void* d_out, int out_size)
{
    const float* values = (const float*)d_in[1];
    const float* Wv     = (const float*)d_in[6];
    const float* Wp     = (const float*)d_in[7];
    float* out          = (float*)d_out;

    build_C_kernel<<<dim3(2, 2, SPLITK), 256>>>(Wv, Wp);
    reduce_C_kernel<<<128, 128>>>();
    gemm_out_kernel<<<dim3(8, 16), 256>>>(values, out);
}